// round 5
// baseline (speedup 1.0000x reference)
#include <cuda_runtime.h>
#include <math.h>

#define N_ROWS   131072
#define IN_D     12
#define HID      256
#define NL       10
#define OUT_D    3
#define TM       64                 // rows per CTA
#define KC       16                 // k-chunk staged per cp.async group
#define NCHUNK   (HID / KC)         // 16 chunks per layer
#define NTHREADS 256
#define TOTAL_CHUNKS ((NL - 1) * NCHUNK)   // 144 flat chunks over hidden layers

typedef unsigned long long u64;

// packed fp32x2 FMA: d = a*b + d (elementwise on two packed floats)
__device__ __forceinline__ void fma2(u64& d, u64 a, u64 b) {
    asm("fma.rn.f32x2 %0, %1, %2, %0;" : "+l"(d) : "l"(a), "l"(b));
}
__device__ __forceinline__ u64 dup2(float v) {
    u64 r;
    asm("mov.b64 %0, {%1, %1};" : "=l"(r) : "f"(v));
    return r;
}
__device__ __forceinline__ float2 unpk2(u64 p) {
    float lo, hi;
    asm("mov.b64 {%0, %1}, %2;" : "=f"(lo), "=f"(hi) : "l"(p));
    return make_float2(lo, hi);
}

// act: 0=sin 1=cos 2=gauss 3=tanh
__device__ __forceinline__ float actf(float v, int mode) {
    switch (mode) {
        case 0:  return sinf(v);
        case 1:  return cosf(v);
        case 2:  return expf(-v * v);
        default: return tanhf(v);
    }
}

// Stage flat chunk tc (16x256 floats) of Ws into wbuf via cp.async (one group).
__device__ __forceinline__ void cp_chunk(const float4* __restrict__ Wv,
                                         int tc, float* wbuf, int tid) {
    const float4* src = Wv + (size_t)tc * (KC * HID / 4) + tid;
    unsigned dst = (unsigned)__cvta_generic_to_shared(wbuf) + tid * 16u;
    #pragma unroll
    for (int r = 0; r < 4; r++) {
        asm volatile("cp.async.cg.shared.global [%0], [%1], 16;\n"
                     :: "r"(dst + r * (NTHREADS * 16u)), "l"(src + r * NTHREADS));
    }
    asm volatile("cp.async.commit_group;\n" ::: "memory");
}

// 8x8 tile k-step using packed FMA: A pairs come straight from smem (m-contig),
// W values are duplicated into both lanes.
// accp[i][j] = rows (m0+2i, m0+2i+1), col (n0+j)
__device__ __forceinline__ void kstep(u64 accp[4][8], const float* hp, const float* wp,
                                      int m0, int n0) {
    const ulonglong2 A0 = *(const ulonglong2*)(hp + m0);      // rows m0..m0+3
    const ulonglong2 A1 = *(const ulonglong2*)(hp + m0 + 4);  // rows m0+4..m0+7
    const float4 w0 = *(const float4*)(wp + n0);
    const float4 w1 = *(const float4*)(wp + n0 + 4);
    u64 Ap[4] = {A0.x, A0.y, A1.x, A1.y};
    u64 wd[8] = {dup2(w0.x), dup2(w0.y), dup2(w0.z), dup2(w0.w),
                 dup2(w1.x), dup2(w1.y), dup2(w1.z), dup2(w1.w)};
    #pragma unroll
    for (int i = 0; i < 4; i++)
        #pragma unroll
        for (int j = 0; j < 8; j++)
            fma2(accp[i][j], Ap[i], wd[j]);
}

__global__ void __launch_bounds__(NTHREADS, 2)
cppn_kernel(const float* __restrict__ x,
            const float* __restrict__ W0,
            const float* __restrict__ b0,
            const float* __restrict__ Ws,
            const float* __restrict__ bs,
            const float* __restrict__ Wout,
            const float* __restrict__ bout,
            float* __restrict__ out)
{
    extern __shared__ float sm[];
    float* hc  = sm;                    // [HID][TM] activations (transposed [k][m]) 64 KB
    float* wb0 = sm + HID * TM;         // [KC][HID] weight stage buffer 0 (16 KB)
    float* wb1 = wb0 + KC * HID;        // [KC][HID] weight stage buffer 1 (16 KB)

    const int tid  = threadIdx.x;
    const int row0 = blockIdx.x * TM;
    const int m0   = (tid & 7) * 8;     // 8 m-rows per thread
    const int n0   = (tid >> 3) * 8;    // 8 n-cols per thread
    const float4* Wv = (const float4*)Ws;

    u64 accp[4][8];
    const u64 Z = 0ull;                 // packed {0.f, 0.f}

    // ---- prologue: start staging hidden chunk 0 into wb0 while layer 0 runs ----
    cp_chunk(Wv, 0, wb0, tid);

    // ======================= layer 0: x(12) -> 256, sin =======================
    {
        float* w0s = wb1;                       // 12 KB
        float* xs  = wb1 + IN_D * HID;          // 3 KB
        const float4* W0v = (const float4*)W0;
        float4* wa = (float4*)w0s;
        #pragma unroll
        for (int idx = tid; idx < IN_D * HID / 4; idx += NTHREADS) wa[idx] = W0v[idx];
        for (int idx = tid; idx < TM * IN_D; idx += NTHREADS) {
            int m = idx / IN_D, k = idx % IN_D;
            xs[k * TM + m] = x[(size_t)(row0 + m) * IN_D + k];
        }
        __syncthreads();

        #pragma unroll
        for (int i = 0; i < 4; i++)
            #pragma unroll
            for (int j = 0; j < 8; j++) accp[i][j] = Z;

        #pragma unroll
        for (int k = 0; k < IN_D; k++)
            kstep(accp, xs + k * TM, w0s + k * HID, m0, n0);

        // bias + sin -> hc
        float4 bv0 = *(const float4*)(b0 + n0);
        float4 bv1 = *(const float4*)(b0 + n0 + 4);
        float bb[8] = {bv0.x,bv0.y,bv0.z,bv0.w,bv1.x,bv1.y,bv1.z,bv1.w};
        #pragma unroll
        for (int j = 0; j < 8; j++) {
            float2 p0 = unpk2(accp[0][j]), p1 = unpk2(accp[1][j]);
            float2 p2 = unpk2(accp[2][j]), p3 = unpk2(accp[3][j]);
            float4 v = { actf(p0.x + bb[j], 0), actf(p0.y + bb[j], 0),
                         actf(p1.x + bb[j], 0), actf(p1.y + bb[j], 0) };
            float4 u = { actf(p2.x + bb[j], 0), actf(p2.y + bb[j], 0),
                         actf(p3.x + bb[j], 0), actf(p3.y + bb[j], 0) };
            *(float4*)(hc + (n0 + j) * TM + m0)     = v;
            *(float4*)(hc + (n0 + j) * TM + m0 + 4) = u;
        }
    }

    // ======================= hidden layers 1..9: 256 -> 256 ===================
    int t = 0;   // flat chunk counter
    for (int layer = 1; layer < NL; layer++) {
        const int mode = layer & 3;

        #pragma unroll
        for (int i = 0; i < 4; i++)
            #pragma unroll
            for (int j = 0; j < 8; j++) accp[i][j] = Z;

        #pragma unroll 1
        for (int c = 0; c < NCHUNK; c++, t++) {
            asm volatile("cp.async.wait_group 0;\n" ::: "memory");
            __syncthreads();
            if (t + 1 < TOTAL_CHUNKS)
                cp_chunk(Wv, t + 1, (t & 1) ? wb0 : wb1, tid);

            const float* Wbuf = (t & 1) ? wb1 : wb0;
            const float* hrow = hc + c * KC * TM;

            #pragma unroll 4
            for (int kk = 0; kk < KC; kk++)
                kstep(accp, hrow + kk * TM, Wbuf + kk * HID, m0, n0);
        }

        // epilogue: all reads of hc for this layer done -> overwrite in place
        __syncthreads();
        const float* bias = bs + (layer - 1) * HID;
        float4 bv0 = *(const float4*)(bias + n0);
        float4 bv1 = *(const float4*)(bias + n0 + 4);
        float bb[8] = {bv0.x,bv0.y,bv0.z,bv0.w,bv1.x,bv1.y,bv1.z,bv1.w};
        #pragma unroll
        for (int j = 0; j < 8; j++) {
            float2 p0 = unpk2(accp[0][j]), p1 = unpk2(accp[1][j]);
            float2 p2 = unpk2(accp[2][j]), p3 = unpk2(accp[3][j]);
            float4 v = { actf(p0.x + bb[j], mode), actf(p0.y + bb[j], mode),
                         actf(p1.x + bb[j], mode), actf(p1.y + bb[j], mode) };
            float4 u = { actf(p2.x + bb[j], mode), actf(p2.y + bb[j], mode),
                         actf(p3.x + bb[j], mode), actf(p3.y + bb[j], mode) };
            *(float4*)(hc + (n0 + j) * TM + m0)     = v;
            *(float4*)(hc + (n0 + j) * TM + m0 + 4) = u;
        }
        // published by the barrier at the top of next layer's first chunk
    }

    // ======================= output layer: 256 -> 3, sigmoid ==================
    __syncthreads();
    if (tid < TM * OUT_D) {                 // 192 threads: one (row, col) each
        const int m = tid / OUT_D;
        const int j = tid % OUT_D;
        float s = bout[j];
        #pragma unroll 8
        for (int k = 0; k < HID; k++)
            s = fmaf(hc[k * TM + m], Wout[k * OUT_D + j], s);
        out[(size_t)(row0 + m) * OUT_D + j] = 1.0f / (1.0f + expf(-s));
    }
}

extern "C" void kernel_launch(void* const* d_in, const int* in_sizes, int n_in,
                              void* d_out, int out_size)
{
    const float* x    = (const float*)d_in[0];
    const float* W0   = (const float*)d_in[1];
    const float* b0   = (const float*)d_in[2];
    const float* Ws   = (const float*)d_in[3];
    const float* bs   = (const float*)d_in[4];
    const float* Wout = (const float*)d_in[5];
    const float* bout = (const float*)d_in[6];
    float* out = (float*)d_out;

    const int smem_bytes = (HID * TM + 2 * KC * HID) * (int)sizeof(float); // 96 KB
    cudaFuncSetAttribute(cppn_kernel, cudaFuncAttributeMaxDynamicSharedMemorySize, smem_bytes);

    dim3 grid(N_ROWS / TM);   // 2048 CTAs, 2 resident per SM
    dim3 block(NTHREADS);
    cppn_kernel<<<grid, block, smem_bytes>>>(x, W0, b0, Ws, bs, Wout, bout, out);
}

// round 8
// speedup vs baseline: 1.2127x; 1.2127x over previous
#include <cuda_runtime.h>
#include <math.h>

#define N_ROWS   131072
#define IN_D     12
#define HID      256
#define NL       10
#define OUT_D    3
#define TM       32                 // rows per CTA
#define KC       16                 // k-chunk staged per cp.async group
#define NCHUNK   (HID / KC)         // 16 chunks per layer
#define NTHREADS 256
#define TOTAL_CHUNKS ((NL - 1) * NCHUNK)   // 144 flat chunks over hidden layers

typedef unsigned long long u64;

// packed fp32x2 FMA: d = a*b + d (elementwise on two packed floats)
__device__ __forceinline__ void fma2(u64& d, u64 a, u64 b) {
    asm("fma.rn.f32x2 %0, %1, %2, %0;" : "+l"(d) : "l"(a), "l"(b));
}
__device__ __forceinline__ u64 dup2(float v) {
    u64 r;
    asm("mov.b64 %0, {%1, %1};" : "=l"(r) : "f"(v));
    return r;
}
__device__ __forceinline__ float2 unpk2(u64 p) {
    float lo, hi;
    asm("mov.b64 {%0, %1}, %2;" : "=f"(lo), "=f"(hi) : "l"(p));
    return make_float2(lo, hi);
}

// act: 0=sin 1=cos 2=gauss 3=tanh
__device__ __forceinline__ float actf(float v, int mode) {
    switch (mode) {
        case 0:  return sinf(v);
        case 1:  return cosf(v);
        case 2:  return expf(-v * v);
        default: return tanhf(v);
    }
}

// Stage flat chunk tc (16x256 floats) of Ws into wbuf via cp.async (one group).
__device__ __forceinline__ void cp_chunk(const float4* __restrict__ Wv,
                                         int tc, float* wbuf, int tid) {
    const float4* src = Wv + (size_t)tc * (KC * HID / 4) + tid;
    unsigned dst = (unsigned)__cvta_generic_to_shared(wbuf) + tid * 16u;
    #pragma unroll
    for (int r = 0; r < 4; r++) {
        asm volatile("cp.async.cg.shared.global [%0], [%1], 16;\n"
                     :: "r"(dst + r * (NTHREADS * 16u)), "l"(src + r * NTHREADS));
    }
    asm volatile("cp.async.commit_group;\n" ::: "memory");
}

// 4m x 8n k-step, n-packed accumulators:
// accp[i][j] = rows m0+i, cols (n0+2j, n0+2j+1).
// W pairs load DIRECTLY as u64 from smem; only 4 a-duplications per k.
__device__ __forceinline__ void kstep(u64 accp[4][4], const float* hp, const float* wp,
                                      int m0, int n0) {
    const float4 av = *(const float4*)(hp + m0);              // 4 m-rows
    const ulonglong2 W0 = *(const ulonglong2*)(wp + n0);      // n-pairs 0,1
    const ulonglong2 W1 = *(const ulonglong2*)(wp + n0 + 4);  // n-pairs 2,3
    u64 ad[4] = {dup2(av.x), dup2(av.y), dup2(av.z), dup2(av.w)};
    u64 wd[4] = {W0.x, W0.y, W1.x, W1.y};
    #pragma unroll
    for (int i = 0; i < 4; i++)
        #pragma unroll
        for (int j = 0; j < 4; j++)
            fma2(accp[i][j], ad[i], wd[j]);
}

__global__ void __launch_bounds__(NTHREADS, 3)
cppn_kernel(const float* __restrict__ x,
            const float* __restrict__ W0,
            const float* __restrict__ b0,
            const float* __restrict__ Ws,
            const float* __restrict__ bs,
            const float* __restrict__ Wout,
            const float* __restrict__ bout,
            float* __restrict__ out)
{
    extern __shared__ float sm[];
    float* hc  = sm;                    // [HID][TM] activations (transposed [k][m]) 32 KB
    float* wb0 = sm + HID * TM;         // [KC][HID] weight stage buffer 0 (16 KB)
    float* wb1 = wb0 + KC * HID;        // [KC][HID] weight stage buffer 1 (16 KB)

    const int tid  = threadIdx.x;
    const int row0 = blockIdx.x * TM;
    const int m0   = (tid & 7) * 4;     // 4 m-rows per thread (8 groups)
    const int n0   = (tid >> 3) * 8;    // 8 n-cols per thread (32 groups)
    const float4* Wv = (const float4*)Ws;

    u64 accp[4][4];
    const u64 Z = 0ull;

    // ---- prologue: start staging hidden chunk 0 into wb0 while layer 0 runs ----
    cp_chunk(Wv, 0, wb0, tid);

    // ======================= layer 0: x(12) -> 256, sin =======================
    {
        float* w0s = wb1;                       // 12 KB
        float* xs  = wb1 + IN_D * HID;          // 1.5 KB
        const float4* W0v = (const float4*)W0;
        float4* wa = (float4*)w0s;
        #pragma unroll
        for (int idx = tid; idx < IN_D * HID / 4; idx += NTHREADS) wa[idx] = W0v[idx];
        for (int idx = tid; idx < TM * IN_D; idx += NTHREADS) {
            int m = idx / IN_D, k = idx % IN_D;
            xs[k * TM + m] = x[(size_t)(row0 + m) * IN_D + k];
        }
        __syncthreads();

        #pragma unroll
        for (int i = 0; i < 4; i++)
            #pragma unroll
            for (int j = 0; j < 4; j++) accp[i][j] = Z;

        #pragma unroll
        for (int k = 0; k < IN_D; k++)
            kstep(accp, xs + k * TM, w0s + k * HID, m0, n0);

        // bias + sin -> hc
        #pragma unroll
        for (int j = 0; j < 4; j++) {
            const float2 bb = *(const float2*)(b0 + n0 + 2 * j);
            float2 p0 = unpk2(accp[0][j]), p1 = unpk2(accp[1][j]);
            float2 p2 = unpk2(accp[2][j]), p3 = unpk2(accp[3][j]);
            float4 ve = { actf(p0.x + bb.x, 0), actf(p1.x + bb.x, 0),
                          actf(p2.x + bb.x, 0), actf(p3.x + bb.x, 0) };
            float4 vo = { actf(p0.y + bb.y, 0), actf(p1.y + bb.y, 0),
                          actf(p2.y + bb.y, 0), actf(p3.y + bb.y, 0) };
            *(float4*)(hc + (n0 + 2 * j) * TM + m0)     = ve;
            *(float4*)(hc + (n0 + 2 * j + 1) * TM + m0) = vo;
        }
    }

    // ======================= hidden layers 1..9: 256 -> 256 ===================
    int t = 0;   // flat chunk counter
    for (int layer = 1; layer < NL; layer++) {
        const int mode = layer & 3;

        #pragma unroll
        for (int i = 0; i < 4; i++)
            #pragma unroll
            for (int j = 0; j < 4; j++) accp[i][j] = Z;

        #pragma unroll 1
        for (int c = 0; c < NCHUNK; c++, t++) {
            asm volatile("cp.async.wait_group 0;\n" ::: "memory");
            __syncthreads();
            if (t + 1 < TOTAL_CHUNKS)
                cp_chunk(Wv, t + 1, (t & 1) ? wb0 : wb1, tid);

            const float* Wbuf = (t & 1) ? wb1 : wb0;
            const float* hrow = hc + c * KC * TM;

            #pragma unroll 4
            for (int kk = 0; kk < KC; kk++)
                kstep(accp, hrow + kk * TM, Wbuf + kk * HID, m0, n0);
        }

        // epilogue: all reads of hc for this layer done -> overwrite in place
        __syncthreads();
        const float* bias = bs + (layer - 1) * HID;
        #pragma unroll
        for (int j = 0; j < 4; j++) {
            const float2 bb = *(const float2*)(bias + n0 + 2 * j);
            float2 p0 = unpk2(accp[0][j]), p1 = unpk2(accp[1][j]);
            float2 p2 = unpk2(accp[2][j]), p3 = unpk2(accp[3][j]);
            float4 ve = { actf(p0.x + bb.x, mode), actf(p1.x + bb.x, mode),
                          actf(p2.x + bb.x, mode), actf(p3.x + bb.x, mode) };
            float4 vo = { actf(p0.y + bb.y, mode), actf(p1.y + bb.y, mode),
                          actf(p2.y + bb.y, mode), actf(p3.y + bb.y, mode) };
            *(float4*)(hc + (n0 + 2 * j) * TM + m0)     = ve;
            *(float4*)(hc + (n0 + 2 * j + 1) * TM + m0) = vo;
        }
        // published by the barrier at the top of next layer's first chunk
    }

    // ======================= output layer: 256 -> 3, sigmoid ==================
    __syncthreads();
    if (tid < TM * OUT_D) {                 // 96 threads: one (row, col) each
        const int m = tid / OUT_D;
        const int j = tid % OUT_D;
        float s = bout[j];
        #pragma unroll 8
        for (int k = 0; k < HID; k++)
            s = fmaf(hc[k * TM + m], Wout[k * OUT_D + j], s);
        out[(size_t)(row0 + m) * OUT_D + j] = 1.0f / (1.0f + expf(-s));
    }
}

extern "C" void kernel_launch(void* const* d_in, const int* in_sizes, int n_in,
                              void* d_out, int out_size)
{
    const float* x    = (const float*)d_in[0];
    const float* W0   = (const float*)d_in[1];
    const float* b0   = (const float*)d_in[2];
    const float* Ws   = (const float*)d_in[3];
    const float* bs   = (const float*)d_in[4];
    const float* Wout = (const float*)d_in[5];
    const float* bout = (const float*)d_in[6];
    float* out = (float*)d_out;

    const int smem_bytes = (HID * TM + 2 * KC * HID) * (int)sizeof(float); // 64 KB
    cudaFuncSetAttribute(cppn_kernel, cudaFuncAttributeMaxDynamicSharedMemorySize, smem_bytes);

    dim3 grid(N_ROWS / TM);   // 4096 CTAs, 3 resident per SM
    dim3 block(NTHREADS);
    cppn_kernel<<<grid, block, smem_bytes>>>(x, W0, b0, Ws, bs, Wout, bout, out);
}